// round 8
// baseline (speedup 1.0000x reference)
#include <cuda_runtime.h>
#include <cuda_bf16.h>
#include <cstdint>

#define NNODE 50000
#define F 128
#define NBLK 49            // ceil(NNODE / 1024)
#define MAXE_TOT 2000000
#define NF ((size_t)NNODE * F)
#define AST 72             // smem row stride in bf16 elems (conflict-free)

// Scratch (sanctioned __device__ globals)
__device__ __nv_bfloat16 g_WThi[5ull * F * F];   // WT hi: [slot][n][k] = bf16(W[k][n])
__device__ __nv_bfloat16 g_WTlo[5ull * F * F];   // WT lo: residual
__device__ int g_cnt[3 * NNODE];
__device__ int g_part[3 * NNODE];
__device__ int g_off[3 * (NNODE + 1)];
__device__ int g_woff[3 * NNODE];
__device__ int g_bs[3 * NBLK];
__device__ int g_csr[MAXE_TOT];
__device__ int g_is64;

// ---------------------------------------------------------------------------
// zero histogram + detect edge dtype (block 0)
// ---------------------------------------------------------------------------
__global__ void zero_detect_kernel(const unsigned* __restrict__ w) {
    int gid = blockIdx.x * blockDim.x + threadIdx.x;
    if (gid < 3 * NNODE) g_cnt[gid] = 0;
    if (blockIdx.x == 0) {
        __shared__ int nz;
        if (threadIdx.x == 0) nz = 0;
        __syncthreads();
        int loc = 0;
        for (int k = threadIdx.x; k < 1024; k += 256)
            if (w[2 * k + 1] != 0) loc = 1;
        if (loc) atomicOr(&nz, 1);
        __syncthreads();
        if (threadIdx.x == 0) g_is64 = (nz == 0);
    }
}

// ---------------------------------------------------------------------------
__global__ void hist_kernel(const void* __restrict__ e0, const void* __restrict__ e1,
                            const void* __restrict__ e2, int E0, int E1, int E2) {
    long long gid = (long long)blockIdx.x * blockDim.x + threadIdx.x;
    const void* e; int rel; long long i; int E;
    if (gid < E0)                           { e = e0; rel = 0; i = gid;            E = E0; }
    else if (gid < (long long)E0 + E1)      { e = e1; rel = 1; i = gid - E0;       E = E1; }
    else if (gid < (long long)E0 + E1 + E2) { e = e2; rel = 2; i = gid - E0 - E1;  E = E2; }
    else return;
    long long d;
    if (g_is64) d = ((const long long*)e)[(long long)E + i];
    else        d = ((const int*)e)[E + i];
    atomicAdd(&g_cnt[rel * NNODE + (int)d], 1);
}

__global__ void scan1_kernel() {
    int rel = blockIdx.x / NBLK, blk = blockIdx.x % NBLK;
    int d = blk * 1024 + threadIdx.x;
    int v = (d < NNODE) ? g_cnt[rel * NNODE + d] : 0;
    int lane = threadIdx.x & 31, w = threadIdx.x >> 5;
    int inc = v;
#pragma unroll
    for (int o = 1; o < 32; o <<= 1) {
        int t = __shfl_up_sync(0xFFFFFFFFu, inc, o);
        if (lane >= o) inc += t;
    }
    __shared__ int wsum[32];
    if (lane == 31) wsum[w] = inc;
    __syncthreads();
    if (w == 0) {
        int t = wsum[lane];
#pragma unroll
        for (int o = 1; o < 32; o <<= 1) {
            int u = __shfl_up_sync(0xFFFFFFFFu, t, o);
            if (lane >= o) t += u;
        }
        wsum[lane] = t;
    }
    __syncthreads();
    int base = (w > 0) ? wsum[w - 1] : 0;
    if (d < NNODE) g_part[rel * NNODE + d] = base + inc - v;
    if (threadIdx.x == 1023) g_bs[rel * NBLK + blk] = base + inc;
}

__global__ void scan2_kernel() {
    int tid = threadIdx.x;
    if (tid < 3) {
        int run = 0;
        for (int b = 0; b < NBLK; b++) {
            int t = g_bs[tid * NBLK + b];
            g_bs[tid * NBLK + b] = run;
            run += t;
        }
    }
}

__global__ void scan3_kernel(int E0, int E1, int E2) {
    int gid = blockIdx.x * blockDim.x + threadIdx.x;
    if (gid >= 3 * (NNODE + 1)) return;
    int rel = gid / (NNODE + 1), d = gid - rel * (NNODE + 1);
    if (d < NNODE) {
        int o = g_part[rel * NNODE + d] + g_bs[rel * NBLK + (d >> 10)];
        g_off[gid] = o;
        g_woff[rel * NNODE + d] = o;
    } else {
        g_off[gid] = (rel == 0) ? E0 : (rel == 1) ? E1 : E2;
    }
}

__global__ void fill_kernel(const void* __restrict__ e0, const void* __restrict__ e1,
                            const void* __restrict__ e2, int E0, int E1, int E2) {
    long long gid = (long long)blockIdx.x * blockDim.x + threadIdx.x;
    const void* e; int rel; long long i; int E; int base;
    if (gid < E0)                           { e = e0; rel = 0; i = gid;           E = E0; base = 0; }
    else if (gid < (long long)E0 + E1)      { e = e1; rel = 1; i = gid - E0;      E = E1; base = E0; }
    else if (gid < (long long)E0 + E1 + E2) { e = e2; rel = 2; i = gid - E0 - E1; E = E2; base = E0 + E1; }
    else return;
    long long s, d;
    if (g_is64) {
        const long long* p = (const long long*)e;
        s = p[i]; d = p[(long long)E + i];
    } else {
        const int* p = (const int*)e;
        s = p[i]; d = p[E + i];
    }
    int pos = atomicAdd(&g_woff[rel * NNODE + (int)d], 1);
    g_csr[base + pos] = (int)s;
}

// ---------------------------------------------------------------------------
__global__ void convW_kernel(const float* __restrict__ W0, const float* __restrict__ W1,
                             const float* __restrict__ W2, const float* __restrict__ W3,
                             const float* __restrict__ W4) {
    const float* W = (blockIdx.x == 0) ? W0 : (blockIdx.x == 1) ? W1 :
                     (blockIdx.x == 2) ? W2 : (blockIdx.x == 3) ? W3 : W4;
    __nv_bfloat16* hi = g_WThi + (size_t)blockIdx.x * F * F;
    __nv_bfloat16* lo = g_WTlo + (size_t)blockIdx.x * F * F;
    for (int idx = threadIdx.x; idx < F * F; idx += blockDim.x) {
        int k = idx >> 7, n = idx & 127;
        float v = W[idx];
        __nv_bfloat16 h = __float2bfloat16(v);
        hi[n * F + k] = h;
        lo[n * F + k] = __float2bfloat16(v - __bfloat162float(h));
    }
}

// ---------------------------------------------------------------------------
// Fused gather + GEMM.  K-chunk = 64.  smem: Ahi|Alo|Bhi|Blo, 128 x AST each.
// ---------------------------------------------------------------------------
__device__ __forceinline__ void mma_bf16(float& c0, float& c1, float& c2, float& c3,
                                         uint32_t a0, uint32_t a1, uint32_t a2, uint32_t a3,
                                         uint32_t b0, uint32_t b1) {
    asm volatile(
        "mma.sync.aligned.m16n8k16.row.col.f32.bf16.bf16.f32 "
        "{%0,%1,%2,%3}, {%4,%5,%6,%7}, {%8,%9}, {%0,%1,%2,%3};"
        : "+f"(c0), "+f"(c1), "+f"(c2), "+f"(c3)
        : "r"(a0), "r"(a1), "r"(a2), "r"(a3), "r"(b0), "r"(b1));
}

__device__ __forceinline__ void stage_dense(
    const float* __restrict__ X, int row0, int ks, int tid,
    __nv_bfloat16* sAhi, __nv_bfloat16* sAlo)
{
#pragma unroll
    for (int t = 0; t < 8; t++) {
        int idx = t * 256 + tid;            // 2048 float4 slots (128 rows x 16)
        int r = idx >> 4, c4 = idx & 15;
        float4 v = make_float4(0.f, 0.f, 0.f, 0.f);
        int gr = row0 + r;
        if (gr < NNODE) v = __ldg((const float4*)(X + (size_t)gr * F + ks) + c4);
        __nv_bfloat16 hx = __float2bfloat16(v.x), hy = __float2bfloat16(v.y);
        __nv_bfloat16 hz = __float2bfloat16(v.z), hw = __float2bfloat16(v.w);
        __nv_bfloat162 h01{hx, hy}, h23{hz, hw};
        __nv_bfloat162 l01{__float2bfloat16(v.x - __bfloat162float(hx)),
                           __float2bfloat16(v.y - __bfloat162float(hy))};
        __nv_bfloat162 l23{__float2bfloat16(v.z - __bfloat162float(hz)),
                           __float2bfloat16(v.w - __bfloat162float(hw))};
        int o = r * AST + c4 * 4;
        *(__nv_bfloat162*)&sAhi[o] = h01;  *(__nv_bfloat162*)&sAhi[o + 2] = h23;
        *(__nv_bfloat162*)&sAlo[o] = l01;  *(__nv_bfloat162*)&sAlo[o + 2] = l23;
    }
}

__device__ __forceinline__ void stage_gather(
    const float* __restrict__ X, const int* __restrict__ csr,
    const int* __restrict__ off, int row0, int ks, int w, int lane,
    __nv_bfloat16* sAhi, __nv_bfloat16* sAlo)
{
    for (int rr = 0; rr < 16; rr++) {
        int r = w * 16 + rr;
        int gr = row0 + r;
        int beg = 0, end = 0;
        if (gr < NNODE) { beg = __ldg(off + gr); end = __ldg(off + gr + 1); }
        int cnt = end - beg;
        float2 acc = make_float2(0.f, 0.f);
        for (int base = 0; base < cnt; base += 32) {
            int nb = min(32, cnt - base);
            int sidx = (lane < nb) ? __ldg(csr + beg + base + lane) : 0;
            int j = 0;
            for (; j + 4 <= nb; j += 4) {
                int s0 = __shfl_sync(0xFFFFFFFFu, sidx, j);
                int s1 = __shfl_sync(0xFFFFFFFFu, sidx, j + 1);
                int s2 = __shfl_sync(0xFFFFFFFFu, sidx, j + 2);
                int s3 = __shfl_sync(0xFFFFFFFFu, sidx, j + 3);
                float2 v0 = __ldg((const float2*)(X + (size_t)s0 * F + ks) + lane);
                float2 v1 = __ldg((const float2*)(X + (size_t)s1 * F + ks) + lane);
                float2 v2 = __ldg((const float2*)(X + (size_t)s2 * F + ks) + lane);
                float2 v3 = __ldg((const float2*)(X + (size_t)s3 * F + ks) + lane);
                acc.x += (v0.x + v1.x) + (v2.x + v3.x);
                acc.y += (v0.y + v1.y) + (v2.y + v3.y);
            }
            for (; j < nb; j++) {
                int s0 = __shfl_sync(0xFFFFFFFFu, sidx, j);
                float2 v0 = __ldg((const float2*)(X + (size_t)s0 * F + ks) + lane);
                acc.x += v0.x; acc.y += v0.y;
            }
        }
        float inv = 1.f / fmaxf((float)cnt, 1.f);
        acc.x *= inv; acc.y *= inv;
        __nv_bfloat16 hx = __float2bfloat16(acc.x), hy = __float2bfloat16(acc.y);
        __nv_bfloat162 h{hx, hy};
        __nv_bfloat162 lo2{__float2bfloat16(acc.x - __bfloat162float(hx)),
                           __float2bfloat16(acc.y - __bfloat162float(hy))};
        *(__nv_bfloat162*)&sAhi[r * AST + lane * 2] = h;
        *(__nv_bfloat162*)&sAlo[r * AST + lane * 2] = lo2;
    }
}

__device__ __forceinline__ void stage_B(
    const __nv_bfloat16* __restrict__ Bh, const __nv_bfloat16* __restrict__ Bl,
    int ks, int tid, __nv_bfloat16* sBhi, __nv_bfloat16* sBlo)
{
#pragma unroll
    for (int t = 0; t < 4; t++) {
        int idx = t * 256 + tid;            // 1024 uint4 slots (128 n x 8)
        int n = idx >> 3, c8 = idx & 7;
        uint4 hv = *(const uint4*)(Bh + (size_t)n * F + ks + c8 * 8);
        uint4 lv = *(const uint4*)(Bl + (size_t)n * F + ks + c8 * 8);
        *(uint4*)&sBhi[n * AST + c8 * 8] = hv;
        *(uint4*)&sBlo[n * AST + c8 * 8] = lv;
    }
}

#define SMEM_BYTES (4 * 128 * AST * 2)   // 73728

__global__ void __launch_bounds__(256, 2) gemm_all(
    const float* __restrict__ xu, const float* __restrict__ xi,
    const float* __restrict__ bias_u, const float* __restrict__ bias_i,
    float* __restrict__ out, int UB, int E0, int E1)
{
    extern __shared__ __nv_bfloat16 sm[];
    __nv_bfloat16* sAhi = sm;
    __nv_bfloat16* sAlo = sm + 128 * AST;
    __nv_bfloat16* sBhi = sm + 2 * 128 * AST;
    __nv_bfloat16* sBlo = sm + 3 * 128 * AST;

    const int tid = threadIdx.x;
    const int w = tid >> 5, l = tid & 31;
    const int mBase = (w >> 2) * 64;
    const int nBase = (w & 3) * 32;
    const int lq = l >> 2;
    const int lr2 = (l & 3) * 2;

    const bool user = (int)blockIdx.x < UB;
    const int bidl = user ? blockIdx.x : blockIdx.x - UB;
    const int row0 = bidl * 128;
    const int nsrc = user ? 3 : 2;
    const float* bias = user ? bias_u : bias_i;
    float* o = user ? out : out + NF;

    float acc[4][4][4];
#pragma unroll
    for (int i = 0; i < 4; i++)
#pragma unroll
        for (int j = 0; j < 4; j++)
#pragma unroll
            for (int q = 0; q < 4; q++) acc[i][j][q] = 0.f;

    for (int s = 0; s < nsrc; s++) {
        int slot, gtype;
        const float* X;
        const int* csr = g_csr;
        const int* off = g_off;
        if (user) {
            if (s == 0)      { slot = 0; X = xu; csr = g_csr;          off = g_off;                   gtype = 1; }
            else if (s == 1) { slot = 1; X = xi; csr = g_csr + E0;     off = g_off + (NNODE + 1);     gtype = 1; }
            else             { slot = 2; X = xu;                                                       gtype = 0; }
        } else {
            if (s == 0)      { slot = 3; X = xu; csr = g_csr + E0 + E1; off = g_off + 2 * (NNODE + 1); gtype = 1; }
            else             { slot = 4; X = xi;                                                       gtype = 0; }
        }
        const __nv_bfloat16* Bh = g_WThi + (size_t)slot * F * F;
        const __nv_bfloat16* Bl = g_WTlo + (size_t)slot * F * F;

        for (int ch = 0; ch < 2; ch++) {
            const int ks = ch * 64;
            if (gtype) stage_gather(X, csr, off, row0, ks, w, l, sAhi, sAlo);
            else       stage_dense(X, row0, ks, tid, sAhi, sAlo);
            stage_B(Bh, Bl, ks, tid, sBhi, sBlo);
            __syncthreads();

#pragma unroll
            for (int kk = 0; kk < 64; kk += 16) {
#pragma unroll
                for (int term = 0; term < 3; term++) {
                    const __nv_bfloat16* pA = (term == 1) ? sAlo : sAhi;
                    const __nv_bfloat16* pB = (term == 2) ? sBlo : sBhi;
                    uint32_t a[4][4], b[4][2];
#pragma unroll
                    for (int i = 0; i < 4; i++) {
                        int ar = mBase + i * 16 + lq;
                        int ac = kk + lr2;
                        a[i][0] = *(const uint32_t*)&pA[ar * AST + ac];
                        a[i][1] = *(const uint32_t*)&pA[(ar + 8) * AST + ac];
                        a[i][2] = *(const uint32_t*)&pA[ar * AST + ac + 8];
                        a[i][3] = *(const uint32_t*)&pA[(ar + 8) * AST + ac + 8];
                    }
#pragma unroll
                    for (int j = 0; j < 4; j++) {
                        int bn = nBase + j * 8 + lq;
                        int bk = kk + lr2;
                        b[j][0] = *(const uint32_t*)&pB[bn * AST + bk];
                        b[j][1] = *(const uint32_t*)&pB[bn * AST + bk + 8];
                    }
#pragma unroll
                    for (int i = 0; i < 4; i++)
#pragma unroll
                        for (int j = 0; j < 4; j++)
                            mma_bf16(acc[i][j][0], acc[i][j][1], acc[i][j][2], acc[i][j][3],
                                     a[i][0], a[i][1], a[i][2], a[i][3], b[j][0], b[j][1]);
                }
            }
            __syncthreads();
        }
    }

    // ---- epilogue: bias + relu + store ----
#pragma unroll
    for (int j = 0; j < 4; j++) {
        int col = nBase + j * 8 + lr2;
        float2 bv = *(const float2*)(bias + col);
#pragma unroll
        for (int i = 0; i < 4; i++) {
            int r0 = row0 + mBase + i * 16 + lq;
            int r1 = r0 + 8;
            if (r0 < NNODE) {
                float2 o0;
                o0.x = fmaxf(acc[i][j][0] + bv.x, 0.f);
                o0.y = fmaxf(acc[i][j][1] + bv.y, 0.f);
                *(float2*)(o + (size_t)r0 * F + col) = o0;
            }
            if (r1 < NNODE) {
                float2 o1;
                o1.x = fmaxf(acc[i][j][2] + bv.x, 0.f);
                o1.y = fmaxf(acc[i][j][3] + bv.y, 0.f);
                *(float2*)(o + (size_t)r1 * F + col) = o1;
            }
        }
    }
}

// ---------------------------------------------------------------------------
extern "C" void kernel_launch(void* const* d_in, const int* in_sizes, int n_in,
                              void* d_out, int out_size) {
    const float* x_user = (const float*)d_in[0];
    const float* x_item = (const float*)d_in[1];
    const void* e_follows   = d_in[2];
    const void* e_buys      = d_in[3];
    const void* e_bought_by = d_in[4];
    const float* W_follows   = (const float*)d_in[5];
    const float* W_buys      = (const float*)d_in[6];
    const float* W_bought_by = (const float*)d_in[7];
    const float* W_loop_user = (const float*)d_in[8];
    const float* b_loop_user = (const float*)d_in[9];
    const float* W_loop_item = (const float*)d_in[10];
    const float* b_loop_item = (const float*)d_in[11];

    // CSR relation order: 0=follows(u->u), 1=bought_by(i->u), 2=buys(u->i)
    int E0 = in_sizes[2] / 2;   // follows
    int E1 = in_sizes[4] / 2;   // bought_by
    int E2 = in_sizes[3] / 2;   // buys

    zero_detect_kernel<<<(3 * NNODE + 255) / 256, 256>>>((const unsigned*)e_follows);

    long long TOT = (long long)E0 + E1 + E2;
    int eblocks = (int)((TOT + 255) / 256);
    hist_kernel<<<eblocks, 256>>>(e_follows, e_bought_by, e_buys, E0, E1, E2);
    scan1_kernel<<<3 * NBLK, 1024>>>();
    scan2_kernel<<<1, 32>>>();
    scan3_kernel<<<(3 * (NNODE + 1) + 255) / 256, 256>>>(E0, E1, E2);
    fill_kernel<<<eblocks, 256>>>(e_follows, e_bought_by, e_buys, E0, E1, E2);

    // W slots: 0=follows, 1=bought_by, 2=loop_user, 3=buys, 4=loop_item
    convW_kernel<<<5, 256>>>(W_follows, W_bought_by, W_loop_user, W_buys, W_loop_item);

    int UB = (NNODE + 127) / 128;   // 391
    cudaFuncSetAttribute(gemm_all, cudaFuncAttributeMaxDynamicSharedMemorySize, SMEM_BYTES);
    gemm_all<<<2 * UB, 256, SMEM_BYTES>>>(x_user, x_item, b_loop_user, b_loop_item,
                                          (float*)d_out, UB, E0, E1);
}

// round 9
// speedup vs baseline: 1.4433x; 1.4433x over previous
#include <cuda_runtime.h>
#include <cuda_bf16.h>
#include <cstdint>

#define NNODE 50000
#define F 128
#define NBLK 49            // ceil(NNODE / 1024)
#define MAXE_TOT 2000000
#define NF ((size_t)NNODE * F)

// Scratch (sanctioned __device__ globals)
__device__ float g_agg[3ull * NNODE * F];        // normalized aggregation [rel][node][feat]
__device__ __nv_bfloat16 g_WThi[5ull * F * F];   // WT hi: [slot][n][k] = bf16(W[k][n])
__device__ __nv_bfloat16 g_WTlo[5ull * F * F];   // WT lo: residual
__device__ int g_cnt[3 * NNODE];
__device__ int g_part[3 * NNODE];
__device__ int g_off[3 * (NNODE + 1)];
__device__ int g_woff[3 * NNODE];
__device__ int g_bs[3 * NBLK];
__device__ int g_csr[MAXE_TOT];
__device__ int g_is64;

// ---------------------------------------------------------------------------
__global__ void detect_kernel(const unsigned* __restrict__ w) {
    __shared__ int nz;
    if (threadIdx.x == 0) nz = 0;
    __syncthreads();
    if (w[2 * threadIdx.x + 1] != 0) atomicOr(&nz, 1);
    __syncthreads();
    if (threadIdx.x == 0) g_is64 = (nz == 0);
}

__global__ void zero_cnt_kernel() {
    int gid = blockIdx.x * blockDim.x + threadIdx.x;
    if (gid < 3 * NNODE) g_cnt[gid] = 0;
}

// ---------------------------------------------------------------------------
__global__ void hist_kernel(const void* __restrict__ e0, const void* __restrict__ e1,
                            const void* __restrict__ e2, int E0, int E1, int E2) {
    long long gid = (long long)blockIdx.x * blockDim.x + threadIdx.x;
    const void* e; int rel; long long i; int E;
    if (gid < E0)                           { e = e0; rel = 0; i = gid;            E = E0; }
    else if (gid < (long long)E0 + E1)      { e = e1; rel = 1; i = gid - E0;       E = E1; }
    else if (gid < (long long)E0 + E1 + E2) { e = e2; rel = 2; i = gid - E0 - E1;  E = E2; }
    else return;
    long long d;
    if (g_is64) d = ((const long long*)e)[(long long)E + i];
    else        d = ((const int*)e)[E + i];
    atomicAdd(&g_cnt[rel * NNODE + (int)d], 1);
}

__global__ void scan1_kernel() {
    int rel = blockIdx.x / NBLK, blk = blockIdx.x % NBLK;
    int d = blk * 1024 + threadIdx.x;
    int v = (d < NNODE) ? g_cnt[rel * NNODE + d] : 0;
    int lane = threadIdx.x & 31, w = threadIdx.x >> 5;
    int inc = v;
#pragma unroll
    for (int o = 1; o < 32; o <<= 1) {
        int t = __shfl_up_sync(0xFFFFFFFFu, inc, o);
        if (lane >= o) inc += t;
    }
    __shared__ int wsum[32];
    if (lane == 31) wsum[w] = inc;
    __syncthreads();
    if (w == 0) {
        int t = wsum[lane];
#pragma unroll
        for (int o = 1; o < 32; o <<= 1) {
            int u = __shfl_up_sync(0xFFFFFFFFu, t, o);
            if (lane >= o) t += u;
        }
        wsum[lane] = t;
    }
    __syncthreads();
    int base = (w > 0) ? wsum[w - 1] : 0;
    if (d < NNODE) g_part[rel * NNODE + d] = base + inc - v;
    if (threadIdx.x == 1023) g_bs[rel * NBLK + blk] = base + inc;
}

__global__ void scan2_kernel() {
    int tid = threadIdx.x;
    if (tid < 3) {
        int run = 0;
        for (int b = 0; b < NBLK; b++) {
            int t = g_bs[tid * NBLK + b];
            g_bs[tid * NBLK + b] = run;
            run += t;
        }
    }
}

__global__ void scan3_kernel(int E0, int E1, int E2) {
    int gid = blockIdx.x * blockDim.x + threadIdx.x;
    if (gid >= 3 * (NNODE + 1)) return;
    int rel = gid / (NNODE + 1), d = gid - rel * (NNODE + 1);
    if (d < NNODE) {
        int o = g_part[rel * NNODE + d] + g_bs[rel * NBLK + (d >> 10)];
        g_off[gid] = o;
        g_woff[rel * NNODE + d] = o;
    } else {
        g_off[gid] = (rel == 0) ? E0 : (rel == 1) ? E1 : E2;
    }
}

__global__ void fill_kernel(const void* __restrict__ e0, const void* __restrict__ e1,
                            const void* __restrict__ e2, int E0, int E1, int E2) {
    long long gid = (long long)blockIdx.x * blockDim.x + threadIdx.x;
    const void* e; int rel; long long i; int E; int base;
    if (gid < E0)                           { e = e0; rel = 0; i = gid;           E = E0; base = 0; }
    else if (gid < (long long)E0 + E1)      { e = e1; rel = 1; i = gid - E0;      E = E1; base = E0; }
    else if (gid < (long long)E0 + E1 + E2) { e = e2; rel = 2; i = gid - E0 - E1; E = E2; base = E0 + E1; }
    else return;
    long long s, d;
    if (g_is64) {
        const long long* p = (const long long*)e;
        s = p[i]; d = p[(long long)E + i];
    } else {
        const int* p = (const int*)e;
        s = p[i]; d = p[E + i];
    }
    int pos = atomicAdd(&g_woff[rel * NNODE + (int)d], 1);
    g_csr[base + pos] = (int)s;
}

// ---------------------------------------------------------------------------
// Gather-aggregate: one warp per (rel, dst). CSR mean-gather, fp32 output.
// ---------------------------------------------------------------------------
__global__ void __launch_bounds__(256) aggregate_kernel(
    const float* __restrict__ xu, const float* __restrict__ xi, int E0, int E1) {
    int lane = threadIdx.x & 31;
    int wid = (int)(((long long)blockIdx.x * blockDim.x + threadIdx.x) >> 5);
    if (wid >= 3 * NNODE) return;
    int rel = wid / NNODE;
    int beg = g_off[wid + rel];       // rel*(NNODE+1)+d == wid+rel
    int end = g_off[wid + rel + 1];
    const float* x = (rel == 1) ? xi : xu;
    const int* csr = g_csr + ((rel == 0) ? 0 : (rel == 1) ? E0 : (E0 + E1));

    float4 acc = make_float4(0.f, 0.f, 0.f, 0.f);
    int j = beg;
    for (; j + 4 <= end; j += 4) {
        int s0 = __ldg(csr + j), s1 = __ldg(csr + j + 1);
        int s2 = __ldg(csr + j + 2), s3 = __ldg(csr + j + 3);
        float4 v0 = __ldg((const float4*)(x + (size_t)s0 * F) + lane);
        float4 v1 = __ldg((const float4*)(x + (size_t)s1 * F) + lane);
        float4 v2 = __ldg((const float4*)(x + (size_t)s2 * F) + lane);
        float4 v3 = __ldg((const float4*)(x + (size_t)s3 * F) + lane);
        acc.x += (v0.x + v1.x) + (v2.x + v3.x);
        acc.y += (v0.y + v1.y) + (v2.y + v3.y);
        acc.z += (v0.z + v1.z) + (v2.z + v3.z);
        acc.w += (v0.w + v1.w) + (v2.w + v3.w);
    }
    for (; j < end; j++) {
        int s0 = __ldg(csr + j);
        float4 v0 = __ldg((const float4*)(x + (size_t)s0 * F) + lane);
        acc.x += v0.x; acc.y += v0.y; acc.z += v0.z; acc.w += v0.w;
    }
    float inv = 1.f / fmaxf((float)(end - beg), 1.f);
    acc.x *= inv; acc.y *= inv; acc.z *= inv; acc.w *= inv;
    ((float4*)(g_agg + (size_t)wid * F))[lane] = acc;
}

// ---------------------------------------------------------------------------
__global__ void convW_kernel(const float* __restrict__ W0, const float* __restrict__ W1,
                             const float* __restrict__ W2, const float* __restrict__ W3,
                             const float* __restrict__ W4) {
    const float* W = (blockIdx.x == 0) ? W0 : (blockIdx.x == 1) ? W1 :
                     (blockIdx.x == 2) ? W2 : (blockIdx.x == 3) ? W3 : W4;
    __nv_bfloat16* hi = g_WThi + (size_t)blockIdx.x * F * F;
    __nv_bfloat16* lo = g_WTlo + (size_t)blockIdx.x * F * F;
    for (int idx = threadIdx.x; idx < F * F; idx += blockDim.x) {
        int k = idx >> 7, n = idx & 127;
        float v = W[idx];
        __nv_bfloat16 h = __float2bfloat16(v);
        hi[n * F + k] = h;
        lo[n * F + k] = __float2bfloat16(v - __bfloat162float(h));
    }
}

// ---------------------------------------------------------------------------
// Fused single-launch tensor-core GEMM (bf16 3-term split, ldmatrix fragments).
//   blocks [0, UB):   user rows — srcs {agg0, agg1, x_user}, W slots {0,1,2}
//   blocks [UB, 2UB): item rows — srcs {agg2, x_item},       W slots {3,4}
// CTA tile 128x128, 8 warps (2x4), warp 64x32, m16n8k16 atoms.
// ---------------------------------------------------------------------------
#define ASTRIDE 40

__device__ __forceinline__ void mma_bf16(float& c0, float& c1, float& c2, float& c3,
                                         uint32_t a0, uint32_t a1, uint32_t a2, uint32_t a3,
                                         uint32_t b0, uint32_t b1) {
    asm volatile(
        "mma.sync.aligned.m16n8k16.row.col.f32.bf16.bf16.f32 "
        "{%0,%1,%2,%3}, {%4,%5,%6,%7}, {%8,%9}, {%0,%1,%2,%3};"
        : "+f"(c0), "+f"(c1), "+f"(c2), "+f"(c3)
        : "r"(a0), "r"(a1), "r"(a2), "r"(a3), "r"(b0), "r"(b1));
}
__device__ __forceinline__ void ldmx4(uint32_t& r0, uint32_t& r1, uint32_t& r2, uint32_t& r3,
                                      uint32_t addr) {
    asm volatile("ldmatrix.sync.aligned.m8n8.x4.shared.b16 {%0,%1,%2,%3}, [%4];"
                 : "=r"(r0), "=r"(r1), "=r"(r2), "=r"(r3) : "r"(addr));
}

__global__ void __launch_bounds__(256, 2) gemm_all(
    const float* __restrict__ xu, const float* __restrict__ xi,
    const float* __restrict__ bias_u, const float* __restrict__ bias_i,
    float* __restrict__ out, int UB)
{
    __shared__ __nv_bfloat16 sAhi[128 * ASTRIDE];
    __shared__ __nv_bfloat16 sAlo[128 * ASTRIDE];
    __shared__ __nv_bfloat16 sBhi[128 * ASTRIDE];
    __shared__ __nv_bfloat16 sBlo[128 * ASTRIDE];

    const int tid = threadIdx.x;
    const int w = tid >> 5, l = tid & 31;
    const int mBase = (w >> 2) * 64;
    const int nBase = (w & 3) * 32;
    const int lq = l >> 2;
    const int lr2 = (l & 3) * 2;

    const bool user = (int)blockIdx.x < UB;
    const int bidl = user ? blockIdx.x : blockIdx.x - UB;
    const int row0 = bidl * 128;
    const int nsrc = user ? 3 : 2;
    const float* bias = user ? bias_u : bias_i;
    float* o = user ? out : out + NF;

    // ldmatrix per-lane offsets (elements):
    //   A x4 matrices: [r0-7|k0-7], [r8-15|k0-7], [r0-7|k8-15], [r8-15|k8-15]
    const int aRow = mBase + (l & 7) + ((l >> 3) & 1) * 8;
    const int aOff = aRow * ASTRIDE + (l >> 4) * 8;
    //   B x4 matrices: [n(j)+0-7|k0-7], [n(j)|k8-15], [n(j+1)|k0-7], [n(j+1)|k8-15]
    const int bRow = (l & 7) + (l >> 4) * 8;
    const int bOff = bRow * ASTRIDE + ((l >> 3) & 1) * 8;

    const uint32_t uAhi = (uint32_t)__cvta_generic_to_shared(sAhi);
    const uint32_t uAlo = (uint32_t)__cvta_generic_to_shared(sAlo);
    const uint32_t uBhi = (uint32_t)__cvta_generic_to_shared(sBhi);
    const uint32_t uBlo = (uint32_t)__cvta_generic_to_shared(sBlo);

    float acc[4][4][4];
#pragma unroll
    for (int i = 0; i < 4; i++)
#pragma unroll
        for (int j = 0; j < 4; j++)
#pragma unroll
            for (int q = 0; q < 4; q++) acc[i][j][q] = 0.f;

    for (int s = 0; s < nsrc; s++) {
        const float* A;
        int slot;
        if (user) {
            A = (s == 0) ? g_agg : (s == 1) ? g_agg + NF : xu;
            slot = s;
        } else {
            A = (s == 0) ? g_agg + 2 * NF : xi;
            slot = 3 + s;
        }
        const __nv_bfloat16* Bh = g_WThi + (size_t)slot * F * F;
        const __nv_bfloat16* Bl = g_WTlo + (size_t)slot * F * F;

        for (int ks = 0; ks < F; ks += 32) {
            // ---- stage A chunk [128 x 32] fp32 -> hi/lo bf16 ----
#pragma unroll
            for (int t = 0; t < 4; t++) {
                int idx = t * 256 + tid;
                int r = idx >> 3, c4 = idx & 7;
                float4 v = make_float4(0.f, 0.f, 0.f, 0.f);
                int gr = row0 + r;
                if (gr < NNODE) v = __ldg((const float4*)(A + (size_t)gr * F + ks) + c4);
                __nv_bfloat16 hx = __float2bfloat16(v.x), hy = __float2bfloat16(v.y);
                __nv_bfloat16 hz = __float2bfloat16(v.z), hw = __float2bfloat16(v.w);
                __nv_bfloat162 h01{hx, hy}, h23{hz, hw};
                __nv_bfloat162 l01{__float2bfloat16(v.x - __bfloat162float(hx)),
                                   __float2bfloat16(v.y - __bfloat162float(hy))};
                __nv_bfloat162 l23{__float2bfloat16(v.z - __bfloat162float(hz)),
                                   __float2bfloat16(v.w - __bfloat162float(hw))};
                int oo = r * ASTRIDE + c4 * 4;
                *(__nv_bfloat162*)&sAhi[oo] = h01;  *(__nv_bfloat162*)&sAhi[oo + 2] = h23;
                *(__nv_bfloat162*)&sAlo[oo] = l01;  *(__nv_bfloat162*)&sAlo[oo + 2] = l23;
            }
            // ---- stage B chunk [128n x 32k] pre-split bf16 ----
#pragma unroll
            for (int t = 0; t < 4; t++) {
                int idx = t * 256 + tid;
                int n = idx >> 3, c4 = idx & 7;
                uint2 hv = *(const uint2*)(Bh + (size_t)n * F + ks + c4 * 4);
                uint2 lv = *(const uint2*)(Bl + (size_t)n * F + ks + c4 * 4);
                int oo = n * ASTRIDE + c4 * 4;
                *(uint2*)&sBhi[oo] = hv;
                *(uint2*)&sBlo[oo] = lv;
            }
            __syncthreads();

#pragma unroll
            for (int kk = 0; kk < 32; kk += 16) {
#pragma unroll
                for (int term = 0; term < 3; term++) {
                    const uint32_t uA = (term == 1) ? uAlo : uAhi;
                    const uint32_t uB = (term == 2) ? uBlo : uBhi;
                    uint32_t a[4][4], b[4][2];
#pragma unroll
                    for (int i = 0; i < 4; i++)
                        ldmx4(a[i][0], a[i][1], a[i][2], a[i][3],
                              uA + (uint32_t)(aOff + i * 16 * ASTRIDE + kk) * 2);
#pragma unroll
                    for (int j = 0; j < 4; j += 2)
                        ldmx4(b[j][0], b[j][1], b[j + 1][0], b[j + 1][1],
                              uB + (uint32_t)(bOff + (nBase + j * 8) * ASTRIDE + kk) * 2);
#pragma unroll
                    for (int i = 0; i < 4; i++)
#pragma unroll
                        for (int j = 0; j < 4; j++)
                            mma_bf16(acc[i][j][0], acc[i][j][1], acc[i][j][2], acc[i][j][3],
                                     a[i][0], a[i][1], a[i][2], a[i][3], b[j][0], b[j][1]);
                }
            }
            __syncthreads();
        }
    }

    // ---- epilogue: bias + relu + store ----
#pragma unroll
    for (int j = 0; j < 4; j++) {
        int col = nBase + j * 8 + lr2;
        float2 bv = *(const float2*)(bias + col);
#pragma unroll
        for (int i = 0; i < 4; i++) {
            int r0 = row0 + mBase + i * 16 + lq;
            int r1 = r0 + 8;
            if (r0 < NNODE) {
                float2 o0;
                o0.x = fmaxf(acc[i][j][0] + bv.x, 0.f);
                o0.y = fmaxf(acc[i][j][1] + bv.y, 0.f);
                *(float2*)(o + (size_t)r0 * F + col) = o0;
            }
            if (r1 < NNODE) {
                float2 o1;
                o1.x = fmaxf(acc[i][j][2] + bv.x, 0.f);
                o1.y = fmaxf(acc[i][j][3] + bv.y, 0.f);
                *(float2*)(o + (size_t)r1 * F + col) = o1;
            }
        }
    }
}

// ---------------------------------------------------------------------------
extern "C" void kernel_launch(void* const* d_in, const int* in_sizes, int n_in,
                              void* d_out, int out_size) {
    const float* x_user = (const float*)d_in[0];
    const float* x_item = (const float*)d_in[1];
    const void* e_follows   = d_in[2];
    const void* e_buys      = d_in[3];
    const void* e_bought_by = d_in[4];
    const float* W_follows   = (const float*)d_in[5];
    const float* W_buys      = (const float*)d_in[6];
    const float* W_bought_by = (const float*)d_in[7];
    const float* W_loop_user = (const float*)d_in[8];
    const float* b_loop_user = (const float*)d_in[9];
    const float* W_loop_item = (const float*)d_in[10];
    const float* b_loop_item = (const float*)d_in[11];

    // CSR relation order: 0=follows(u->u), 1=bought_by(i->u), 2=buys(u->i)
    int E0 = in_sizes[2] / 2;   // follows
    int E1 = in_sizes[4] / 2;   // bought_by
    int E2 = in_sizes[3] / 2;   // buys

    detect_kernel<<<1, 1024>>>((const unsigned*)e_follows);
    zero_cnt_kernel<<<(3 * NNODE + 255) / 256, 256>>>();

    long long TOT = (long long)E0 + E1 + E2;
    int eblocks = (int)((TOT + 255) / 256);
    hist_kernel<<<eblocks, 256>>>(e_follows, e_bought_by, e_buys, E0, E1, E2);
    scan1_kernel<<<3 * NBLK, 1024>>>();
    scan2_kernel<<<1, 32>>>();
    scan3_kernel<<<(3 * (NNODE + 1) + 255) / 256, 256>>>(E0, E1, E2);
    fill_kernel<<<eblocks, 256>>>(e_follows, e_bought_by, e_buys, E0, E1, E2);

    // W slots: 0=follows, 1=bought_by, 2=loop_user, 3=buys, 4=loop_item
    convW_kernel<<<5, 256>>>(W_follows, W_bought_by, W_loop_user, W_buys, W_loop_item);

    aggregate_kernel<<<(int)((3ll * NNODE * 32 + 255) / 256), 256>>>(x_user, x_item, E0, E1);

    int UB = (NNODE + 127) / 128;   // 391
    gemm_all<<<2 * UB, 256>>>(x_user, x_item, b_loop_user, b_loop_item,
                              (float*)d_out, UB);
}